// round 11
// baseline (speedup 1.0000x reference)
#include <cuda_runtime.h>
#include <cuda_fp16.h>
#include <cstdint>

// out = residual + s * HS @ (w_up w2 w1 w_down)^T
// wA = w2@w1@w_down [512,2048] precomputed in fp16 (two tiny GEMMs), then:
//   o   = HS @ wA^T  (A converted fp32->fp16 inside the loader)
//   out = res + s*(o @ w_up^T)
// Big GEMMs: fp16 HMMA with fp16 accumulators flushed to fp32 every K=128
// (2x tensor rate, bounded rounding). Small GEMMs: fp32 accum.

#define M_TOTAL 8192
#define H_Q 2048
#define H_S 512

typedef __half hf;

// ---- device scratch ----
__device__ hf g_wup_h[H_Q * H_S];
__device__ hf g_w2_h[H_S * H_S];
__device__ hf g_w1T_h[H_S * H_S];
__device__ hf g_wdT_h[H_Q * H_S];
__device__ hf g_tmp_h[H_S * H_S];
__device__ hf g_wA_h[H_S * H_Q];
__device__ hf g_o_h[M_TOTAL * H_S];

// ---------------- helpers ----------------
static __device__ __forceinline__ uint32_t s2u(const void* p) {
    uint32_t a;
    asm("{ .reg .u64 t; cvta.to.shared.u64 t, %1; cvt.u32.u64 %0, t; }"
        : "=r"(a) : "l"(p));
    return a;
}
static __device__ __forceinline__ void cp16(uint32_t s, const void* g) {
    asm volatile("cp.async.cg.shared.global [%0], [%1], 16;" :: "r"(s), "l"(g));
}
static __device__ __forceinline__ void ldm_x4(uint32_t* r, uint32_t addr) {
    asm volatile("ldmatrix.sync.aligned.m8n8.x4.shared.b16 {%0,%1,%2,%3}, [%4];"
                 : "=r"(r[0]), "=r"(r[1]), "=r"(r[2]), "=r"(r[3]) : "r"(addr));
}
static __device__ __forceinline__ void mma_f32acc(float* c, const uint32_t* a,
                                                  const uint32_t* b) {
    asm volatile(
        "mma.sync.aligned.m16n8k16.row.col.f32.f16.f16.f32 "
        "{%0,%1,%2,%3}, {%4,%5,%6,%7}, {%8,%9}, {%0,%1,%2,%3};"
        : "+f"(c[0]), "+f"(c[1]), "+f"(c[2]), "+f"(c[3])
        : "r"(a[0]), "r"(a[1]), "r"(a[2]), "r"(a[3]), "r"(b[0]), "r"(b[1]));
}
static __device__ __forceinline__ void mma_f16acc(uint32_t* c, const uint32_t* a,
                                                  const uint32_t* b) {
    asm volatile(
        "mma.sync.aligned.m16n8k16.row.col.f16.f16.f16.f16 "
        "{%0,%1}, {%2,%3,%4,%5}, {%6,%7}, {%0,%1};"
        : "+r"(c[0]), "+r"(c[1])
        : "r"(a[0]), "r"(a[1]), "r"(a[2]), "r"(a[3]), "r"(b[0]), "r"(b[1]));
}
static __device__ __forceinline__ uint32_t pack_hf(float a, float b) {
    __half2 p = __floats2half2_rn(a, b);
    return *reinterpret_cast<uint32_t*>(&p);
}

// ---------------- prep: transposes + converts, one kernel ----------------
__global__ __launch_bounds__(256) void prep_all(
    const float* w1, hf* w1T_h,
    const float* wd, hf* wdT_h,
    const float4* wu, __half2* wu_h,
    const float4* w2, __half2* w2_h)
{
    __shared__ float s[32][33];
    int b = blockIdx.x;
    int tid = threadIdx.x;
    if (b < 1280) {
        const float* in; hf* o; int R, C, bx, by;
        if (b < 256) { in = w1; o = w1T_h; R = 512; C = 512;
                       bx = b & 15; by = b >> 4; }
        else         { in = wd; o = wdT_h; R = 512; C = 2048;
                       b -= 256; bx = b & 63; by = b >> 6; }
        int tx = tid & 31, ty = tid >> 5;
#pragma unroll
        for (int j = 0; j < 4; j++)
            s[ty + j * 8][tx] = in[(size_t)(by * 32 + ty + j * 8) * C + bx * 32 + tx];
        __syncthreads();
#pragma unroll
        for (int j = 0; j < 4; j++) {
            size_t off = (size_t)(bx * 32 + ty + j * 8) * R + by * 32 + tx;
            o[off] = __float2half_rn(s[tx][ty + j * 8]);
        }
    } else {
        const float4* src; __half2* dst; int i;
        if (b < 2304) { src = wu; dst = wu_h; i = (b - 1280) * 256 + tid; }
        else          { src = w2; dst = w2_h; i = (b - 2304) * 256 + tid; }
        float4 v = src[i];
        dst[i * 2 + 0] = __floats2half2_rn(v.x, v.y);
        dst[i * 2 + 1] = __floats2half2_rn(v.z, v.w);
    }
}

// ---------------- fp16 HMMA GEMM ----------------
// WM x WN warps, warp tile (MI*16)x(NI*8); CTA BM x BN; BK=32, rows padded
// to 40 halves (80 B). B: S-stage cp.async. A: AF32 -> fp32 LDG+cvt+STS
// double-buffered (needs BM=128, 256 thr); else cp.async S-stage.
// FACC=1: fp16 accumulators flushed to fp32 every 4 k-chunks (K=128).
// MODE 1: Cf = residual + scale*C. MODE 2: C -> fp16.
#define ROWB 80

template <int MI, int NI, int WM, int WN, int S, int MODE, int OCC, int AF32, int FACC>
__global__ __launch_bounds__(32 * WM * WN, OCC) void gemm_mma(
    const hf* __restrict__ A, const float* __restrict__ Af,
    const hf* __restrict__ B,
    int N, int K,
    hf* __restrict__ Ch, float* __restrict__ Cf,
    const float* __restrict__ residual, const float* __restrict__ scale_p)
{
    constexpr int NTHR = 32 * WM * WN;
    constexpr int BM = WM * MI * 16;
    constexpr int BN = WN * NI * 8;
    constexpr int TA_B = BM * ROWB;
    constexpr int TB_B = BN * ROWB;
    constexpr int ASTG = AF32 ? 2 : S;
    constexpr int NCHB = BN * 4 / NTHR;
    constexpr int NCHA = BM * 4 / NTHR;
    static_assert(!AF32 || (BM == 128 && NTHR == 256), "AF32 loader shape");

    extern __shared__ char smem[];
    const uint32_t sb = s2u(smem);
    const uint32_t offB0 = (uint32_t)(ASTG * TA_B);
    const int tid = threadIdx.x;
    const int lane = tid & 31, wid = tid >> 5;
    const int wm = wid % WM, wn = wid / WM;
    const int bm = blockIdx.y * BM, bn = blockIdx.x * BN;

    const hf* srcA = AF32 ? nullptr : (A + (size_t)bm * K);
    const float* srcAf = AF32 ? (Af + (size_t)bm * K) : nullptr;
    const hf* srcB = B + (size_t)bn * K;

    float acc[MI][NI][4];
#pragma unroll
    for (int i = 0; i < MI; i++)
#pragma unroll
        for (int j = 0; j < NI; j++)
#pragma unroll
            for (int q = 0; q < 4; q++) acc[i][j][q] = 0.0f;
    uint32_t a16[FACC ? MI : 1][FACC ? NI : 1][2];
    if (FACC) {
#pragma unroll
        for (int i = 0; i < MI; i++)
#pragma unroll
            for (int j = 0; j < NI; j++)
                a16[i][j][0] = a16[i][j][1] = 0u;
    }

    const int nk = K >> 5;

    auto flush16 = [&]() {
        if (!FACC) return;
#pragma unroll
        for (int i = 0; i < MI; i++)
#pragma unroll
            for (int j = 0; j < NI; j++) {
                float2 f0 = __half22float2(*reinterpret_cast<__half2*>(&a16[i][j][0]));
                float2 f1 = __half22float2(*reinterpret_cast<__half2*>(&a16[i][j][1]));
                acc[i][j][0] += f0.x; acc[i][j][1] += f0.y;
                acc[i][j][2] += f1.x; acc[i][j][3] += f1.y;
                a16[i][j][0] = 0u; a16[i][j][1] = 0u;
            }
    };

    auto issueB = [&](int kc) {
        const int k0 = kc << 5;
        const uint32_t base = sb + offB0 + (uint32_t)(kc % S) * TB_B;
#pragma unroll
        for (int it = 0; it < NCHB; it++) {
            const int c = tid + it * NTHR;
            const int row = c >> 2, col = c & 3;
            cp16(base + row * ROWB + col * 16,
                 srcB + (size_t)row * K + k0 + col * 8);
        }
    };
    auto issueA_cp = [&](int kc) {
        const int k0 = kc << 5;
        const uint32_t base = sb + (uint32_t)(kc % S) * TA_B;
#pragma unroll
        for (int it = 0; it < NCHA; it++) {
            const int c = tid + it * NTHR;
            const int row = c >> 2, col = c & 3;
            cp16(base + row * ROWB + col * 16,
                 srcA + (size_t)row * K + k0 + col * 8);
        }
    };

    // AF32 A path (BM=128, NTHR=256: 2 tasks/thread, 8 floats each)
    float4 areg[2][2];
    auto ldgA = [&](int kc) {
        if (!AF32 || kc >= nk) return;
        const int k0 = kc << 5;
#pragma unroll
        for (int t2 = 0; t2 < 2; t2++) {
            const int q = tid + t2 * NTHR;
            const int row = q >> 2, cg = q & 3;
            const float* p = srcAf + (size_t)row * K + k0 + cg * 8;
            areg[t2][0] = *reinterpret_cast<const float4*>(p);
            areg[t2][1] = *reinterpret_cast<const float4*>(p + 4);
        }
    };
    auto stsA = [&](int kc) {
        if (!AF32) return;
        char* base = smem + (size_t)(kc & 1) * TA_B;
#pragma unroll
        for (int t2 = 0; t2 < 2; t2++) {
            const int q = tid + t2 * NTHR;
            const int row = q >> 2, cg = q & 3;
            uint4 v;
            v.x = pack_hf(areg[t2][0].x, areg[t2][0].y);
            v.y = pack_hf(areg[t2][0].z, areg[t2][0].w);
            v.z = pack_hf(areg[t2][1].x, areg[t2][1].y);
            v.w = pack_hf(areg[t2][1].z, areg[t2][1].w);
            *reinterpret_cast<uint4*>(base + row * ROWB + cg * 16) = v;
        }
    };

    // ---- prologue ----
    if (AF32) {
        ldgA(0);
        stsA(0);
        ldgA(1);
#pragma unroll
        for (int i = 0; i < S - 1; i++) {
            if (i < nk) issueB(i);
            asm volatile("cp.async.commit_group;" ::: "memory");
        }
    } else {
#pragma unroll
        for (int i = 0; i < S - 1; i++) {
            if (i < nk) { issueA_cp(i); issueB(i); }
            asm volatile("cp.async.commit_group;" ::: "memory");
        }
    }

    for (int kc = 0; kc < nk; kc++) {
        asm volatile("cp.async.wait_group %0;" :: "n"(S - 2) : "memory");
        __syncthreads();
        if (AF32 && kc + 1 < nk) { stsA(kc + 1); ldgA(kc + 2); }
        if (kc + S - 1 < nk) {
            if (!AF32) issueA_cp(kc + S - 1);
            issueB(kc + S - 1);
        }
        asm volatile("cp.async.commit_group;" ::: "memory");

        const uint32_t stA = sb + (uint32_t)((AF32 ? (kc & 1) : (kc % S)) * TA_B);
        const uint32_t stB = sb + offB0 + (uint32_t)(kc % S) * TB_B;
#pragma unroll
        for (int ks = 0; ks < 2; ks++) {
            uint32_t ah[MI][4], bb[NI / 2][4];
            const uint32_t aoff = (uint32_t)((wm * MI * 16 + (lane & 15)) * ROWB +
                                             ks * 32 + ((lane >> 4) & 1) * 16);
            const uint32_t boff = (uint32_t)((wn * NI * 8 + ((lane >> 4) & 1) * 8 +
                                              (lane & 7)) * ROWB +
                                             ks * 32 + ((lane >> 3) & 1) * 16);
#pragma unroll
            for (int mi = 0; mi < MI; mi++)
                ldm_x4(ah[mi], stA + aoff + mi * 16 * ROWB);
#pragma unroll
            for (int nj = 0; nj < NI / 2; nj++)
                ldm_x4(bb[nj], stB + boff + nj * 16 * ROWB);
#pragma unroll
            for (int ni = 0; ni < NI; ni++)
#pragma unroll
                for (int mi = 0; mi < MI; mi++) {
                    if (FACC)
                        mma_f16acc(a16[mi][ni], ah[mi], &bb[ni >> 1][2 * (ni & 1)]);
                    else
                        mma_f32acc(acc[mi][ni], ah[mi], &bb[ni >> 1][2 * (ni & 1)]);
                }
        }
        if (FACC && ((kc & 3) == 3)) flush16();
    }
    if (FACC && (nk & 3)) flush16();   // tail (nk divisible by 4 here, safe anyway)

    // ---- epilogue ----
    const float sc = (MODE == 1) ? *scale_p : 0.0f;
    const int er = lane >> 2, ec = 2 * (lane & 3);
#pragma unroll
    for (int mi = 0; mi < MI; mi++)
#pragma unroll
        for (int ni = 0; ni < NI; ni++) {
            const float* a4 = acc[mi][ni];
            const int m0 = bm + wm * MI * 16 + mi * 16 + er;
            const int n0 = bn + wn * NI * 8 + ni * 8 + ec;
#pragma unroll
            for (int h = 0; h < 2; h++) {
                const size_t off = (size_t)(m0 + 8 * h) * N + n0;
                if (MODE == 2) {
                    *reinterpret_cast<__half2*>(Ch + off) =
                        __floats2half2_rn(a4[2 * h + 0], a4[2 * h + 1]);
                } else {
                    float2 r = *reinterpret_cast<const float2*>(residual + off);
                    float2 o;
                    o.x = r.x + sc * a4[2 * h + 0];
                    o.y = r.y + sc * a4[2 * h + 1];
                    *reinterpret_cast<float2*>(Cf + off) = o;
                }
            }
        }
}

// smem sizes
#define TA128  (128 * ROWB)
#define TB256  (256 * ROWB)
#define TB128  (128 * ROWB)
#define TILE64 (64 * ROWB)
#define SMEM_G4 (2 * TA128 + 4 * TB256)     // AF32 A 2 stg + B 4 -> 102400
#define SMEM_G5 (4 * TA128 + 4 * TB128)     // 81920
#define SMEM_SM (4 * TILE64 + 4 * TILE64)   // 40960

// ---------------- host ----------------
extern "C" void kernel_launch(void* const* d_in, const int* in_sizes, int n_in,
                              void* d_out, int out_size) {
    const float* hs     = (const float*)d_in[0];
    const float* w_down = (const float*)d_in[1];
    const float* w_up   = (const float*)d_in[2];
    const float* w1     = (const float*)d_in[3];
    const float* w2     = (const float*)d_in[4];
    const float* scale  = (const float*)d_in[5];
    float* out          = (float*)d_out;

#define SYM(p, s) cudaGetSymbolAddress((void**)&p, s)
    hf *wu_h, *w2_h, *w1T_h, *wdT_h, *tmp_h, *wA_h, *o_h;
    SYM(wu_h, g_wup_h); SYM(w2_h, g_w2_h);
    SYM(w1T_h, g_w1T_h); SYM(wdT_h, g_wdT_h);
    SYM(tmp_h, g_tmp_h); SYM(wA_h, g_wA_h);
    SYM(o_h, g_o_h);
#undef SYM

    // GEMM4: CTA 128x256, 8 warps (2x4), warp 64x64, fp16-acc, AF32 loader
    cudaFuncSetAttribute((const void*)gemm_mma<4, 8, 2, 4, 4, 2, 1, 1, 1>,
                         cudaFuncAttributeMaxDynamicSharedMemorySize, SMEM_G4);
    // GEMM5: CTA 128x128, 16 warps (4x4), warp 32x32, fp16-acc
    cudaFuncSetAttribute((const void*)gemm_mma<2, 4, 4, 4, 4, 1, 1, 0, 1>,
                         cudaFuncAttributeMaxDynamicSharedMemorySize, SMEM_G5);
    // small: CTA 64x64, 4 warps, fp32-acc
    cudaFuncSetAttribute((const void*)gemm_mma<2, 4, 2, 2, 4, 2, 4, 0, 0>,
                         cudaFuncAttributeMaxDynamicSharedMemorySize, SMEM_SM);

    // 0: all prep (transposes + converts)
    prep_all<<<2560, 256>>>(w1, w1T_h, w_down, wdT_h,
                            (const float4*)w_up, (__half2*)wu_h,
                            (const float4*)w2, (__half2*)w2_h);

    // 1: tmp = w2 @ w1  (M=512, N=512, K=512)
    gemm_mma<2, 4, 2, 2, 4, 2, 4, 0, 0><<<dim3(8, 8), 128, SMEM_SM>>>(
        w2_h, nullptr, w1T_h, 512, 512, tmp_h, nullptr, nullptr, nullptr);

    // 2: wA = tmp @ w_down  (M=512, N=2048, K=512)
    gemm_mma<2, 4, 2, 2, 4, 2, 4, 0, 0><<<dim3(32, 8), 128, SMEM_SM>>>(
        tmp_h, nullptr, wdT_h, 2048, 512, wA_h, nullptr, nullptr, nullptr);

    // 3: o = hs @ wA^T  (M=8192, N=512, K=2048; fp16 acc + flush)
    gemm_mma<4, 8, 2, 4, 4, 2, 1, 1, 1><<<dim3(2, 64), 256, SMEM_G4>>>(
        nullptr, hs, wA_h, 512, 2048, o_h, nullptr, nullptr, nullptr);

    // 4: out = res + s * (o @ w_up^T)  (M=8192, N=2048, K=512; fp16 acc + flush)
    gemm_mma<2, 4, 4, 4, 4, 1, 1, 0, 1><<<dim3(16, 64), 512, SMEM_G5>>>(
        o_h, nullptr, wu_h, 2048, 512, nullptr, out, hs, scale);
}

// round 12
// speedup vs baseline: 1.1703x; 1.1703x over previous
#include <cuda_runtime.h>
#include <cuda_fp16.h>
#include <cstdint>

// out = residual + s * HS @ (w_up w2 w1 w_down)^T
// wA = w2@w1@w_down [512,2048] precomputed in fp16 (two tiny GEMMs), then:
//   o   = HS @ wA^T  (A converted fp32->fp16 inside the loader; CTA 128x256)
//   out = res + s*(o @ w_up^T)  (CTA 128x128, 2 CTA/SM)
// All GEMMs: C = A*B^T, K contiguous both sides. fp16 HMMA, fp32 accum
// (fp16-acc measured same rate on sm_103 -> no benefit, reverted).

#define M_TOTAL 8192
#define H_Q 2048
#define H_S 512

typedef __half hf;

// ---- device scratch ----
__device__ hf g_wup_h[H_Q * H_S];
__device__ hf g_w2_h[H_S * H_S];
__device__ hf g_w1T_h[H_S * H_S];
__device__ hf g_wdT_h[H_Q * H_S];
__device__ hf g_tmp_h[H_S * H_S];
__device__ hf g_wA_h[H_S * H_Q];
__device__ hf g_o_h[M_TOTAL * H_S];

// ---------------- helpers ----------------
static __device__ __forceinline__ uint32_t s2u(const void* p) {
    uint32_t a;
    asm("{ .reg .u64 t; cvta.to.shared.u64 t, %1; cvt.u32.u64 %0, t; }"
        : "=r"(a) : "l"(p));
    return a;
}
static __device__ __forceinline__ void cp16(uint32_t s, const void* g) {
    asm volatile("cp.async.cg.shared.global [%0], [%1], 16;" :: "r"(s), "l"(g));
}
static __device__ __forceinline__ void ldm_x4(uint32_t* r, uint32_t addr) {
    asm volatile("ldmatrix.sync.aligned.m8n8.x4.shared.b16 {%0,%1,%2,%3}, [%4];"
                 : "=r"(r[0]), "=r"(r[1]), "=r"(r[2]), "=r"(r[3]) : "r"(addr));
}
static __device__ __forceinline__ void mma_f16(float* c, const uint32_t* a,
                                               const uint32_t* b) {
    asm volatile(
        "mma.sync.aligned.m16n8k16.row.col.f32.f16.f16.f32 "
        "{%0,%1,%2,%3}, {%4,%5,%6,%7}, {%8,%9}, {%0,%1,%2,%3};"
        : "+f"(c[0]), "+f"(c[1]), "+f"(c[2]), "+f"(c[3])
        : "r"(a[0]), "r"(a[1]), "r"(a[2]), "r"(a[3]), "r"(b[0]), "r"(b[1]));
}
static __device__ __forceinline__ uint32_t pack_hf(float a, float b) {
    __half2 p = __floats2half2_rn(a, b);
    return *reinterpret_cast<uint32_t*>(&p);
}

// ---------------- prep: transposes + converts, one kernel ----------------
__global__ __launch_bounds__(256) void prep_all(
    const float* w1, hf* w1T_h,
    const float* wd, hf* wdT_h,
    const float4* wu, __half2* wu_h,
    const float4* w2, __half2* w2_h)
{
    __shared__ float s[32][33];
    int b = blockIdx.x;
    int tid = threadIdx.x;
    if (b < 1280) {
        const float* in; hf* o; int R, C, bx, by;
        if (b < 256) { in = w1; o = w1T_h; R = 512; C = 512;
                       bx = b & 15; by = b >> 4; }
        else         { in = wd; o = wdT_h; R = 512; C = 2048;
                       b -= 256; bx = b & 63; by = b >> 6; }
        int tx = tid & 31, ty = tid >> 5;
#pragma unroll
        for (int j = 0; j < 4; j++)
            s[ty + j * 8][tx] = in[(size_t)(by * 32 + ty + j * 8) * C + bx * 32 + tx];
        __syncthreads();
#pragma unroll
        for (int j = 0; j < 4; j++) {
            size_t off = (size_t)(bx * 32 + ty + j * 8) * R + by * 32 + tx;
            o[off] = __float2half_rn(s[tx][ty + j * 8]);
        }
    } else {
        const float4* src; __half2* dst; int i;
        if (b < 2304) { src = wu; dst = wu_h; i = (b - 1280) * 256 + tid; }
        else          { src = w2; dst = w2_h; i = (b - 2304) * 256 + tid; }
        float4 v = src[i];
        dst[i * 2 + 0] = __floats2half2_rn(v.x, v.y);
        dst[i * 2 + 1] = __floats2half2_rn(v.z, v.w);
    }
}

// ---------------- fp16 HMMA GEMM (fp32 accum) ----------------
// WM x WN warps, warp tile (MI*16)x(NI*8); CTA BM x BN; BK=32, rows padded
// to 40 halves (80 B). B: S-stage cp.async. A: AF32 -> fp32 LDG+cvt+STS
// double-buffered (needs BM=128, 256 thr); else cp.async S-stage.
// MODE 1: Cf = residual + scale*C. MODE 2: C -> fp16.
#define ROWB 80

template <int MI, int NI, int WM, int WN, int S, int MODE, int OCC, int AF32>
__global__ __launch_bounds__(32 * WM * WN, OCC) void gemm_mma(
    const hf* __restrict__ A, const float* __restrict__ Af,
    const hf* __restrict__ B,
    int N, int K,
    hf* __restrict__ Ch, float* __restrict__ Cf,
    const float* __restrict__ residual, const float* __restrict__ scale_p)
{
    constexpr int NTHR = 32 * WM * WN;
    constexpr int BM = WM * MI * 16;
    constexpr int BN = WN * NI * 8;
    constexpr int TA_B = BM * ROWB;
    constexpr int TB_B = BN * ROWB;
    constexpr int ASTG = AF32 ? 2 : S;
    constexpr int NCHB = BN * 4 / NTHR;
    constexpr int NCHA = BM * 4 / NTHR;
    static_assert(!AF32 || (BM == 128 && NTHR == 256), "AF32 loader shape");

    extern __shared__ char smem[];
    const uint32_t sb = s2u(smem);
    const uint32_t offB0 = (uint32_t)(ASTG * TA_B);
    const int tid = threadIdx.x;
    const int lane = tid & 31, wid = tid >> 5;
    const int wm = wid % WM, wn = wid / WM;
    const int bm = blockIdx.y * BM, bn = blockIdx.x * BN;

    const hf* srcA = AF32 ? nullptr : (A + (size_t)bm * K);
    const float* srcAf = AF32 ? (Af + (size_t)bm * K) : nullptr;
    const hf* srcB = B + (size_t)bn * K;

    float acc[MI][NI][4];
#pragma unroll
    for (int i = 0; i < MI; i++)
#pragma unroll
        for (int j = 0; j < NI; j++)
#pragma unroll
            for (int q = 0; q < 4; q++) acc[i][j][q] = 0.0f;

    const int nk = K >> 5;

    auto issueB = [&](int kc) {
        const int k0 = kc << 5;
        const uint32_t base = sb + offB0 + (uint32_t)(kc % S) * TB_B;
#pragma unroll
        for (int it = 0; it < NCHB; it++) {
            const int c = tid + it * NTHR;
            const int row = c >> 2, col = c & 3;
            cp16(base + row * ROWB + col * 16,
                 srcB + (size_t)row * K + k0 + col * 8);
        }
    };
    auto issueA_cp = [&](int kc) {
        const int k0 = kc << 5;
        const uint32_t base = sb + (uint32_t)(kc % S) * TA_B;
#pragma unroll
        for (int it = 0; it < NCHA; it++) {
            const int c = tid + it * NTHR;
            const int row = c >> 2, col = c & 3;
            cp16(base + row * ROWB + col * 16,
                 srcA + (size_t)row * K + k0 + col * 8);
        }
    };

    // AF32 A path (BM=128, NTHR=256: 2 tasks/thread, 8 floats each)
    float4 areg[2][2];
    auto ldgA = [&](int kc) {
        if (!AF32 || kc >= nk) return;
        const int k0 = kc << 5;
#pragma unroll
        for (int t2 = 0; t2 < 2; t2++) {
            const int q = tid + t2 * NTHR;
            const int row = q >> 2, cg = q & 3;
            const float* p = srcAf + (size_t)row * K + k0 + cg * 8;
            areg[t2][0] = *reinterpret_cast<const float4*>(p);
            areg[t2][1] = *reinterpret_cast<const float4*>(p + 4);
        }
    };
    auto stsA = [&](int kc) {
        if (!AF32) return;
        char* base = smem + (size_t)(kc & 1) * TA_B;
#pragma unroll
        for (int t2 = 0; t2 < 2; t2++) {
            const int q = tid + t2 * NTHR;
            const int row = q >> 2, cg = q & 3;
            uint4 v;
            v.x = pack_hf(areg[t2][0].x, areg[t2][0].y);
            v.y = pack_hf(areg[t2][0].z, areg[t2][0].w);
            v.z = pack_hf(areg[t2][1].x, areg[t2][1].y);
            v.w = pack_hf(areg[t2][1].z, areg[t2][1].w);
            *reinterpret_cast<uint4*>(base + row * ROWB + cg * 16) = v;
        }
    };

    // ---- prologue ----
    if (AF32) {
        ldgA(0);
        stsA(0);
        ldgA(1);
#pragma unroll
        for (int i = 0; i < S - 1; i++) {
            if (i < nk) issueB(i);
            asm volatile("cp.async.commit_group;" ::: "memory");
        }
    } else {
#pragma unroll
        for (int i = 0; i < S - 1; i++) {
            if (i < nk) { issueA_cp(i); issueB(i); }
            asm volatile("cp.async.commit_group;" ::: "memory");
        }
    }

    for (int kc = 0; kc < nk; kc++) {
        asm volatile("cp.async.wait_group %0;" :: "n"(S - 2) : "memory");
        __syncthreads();
        if (AF32 && kc + 1 < nk) { stsA(kc + 1); ldgA(kc + 2); }
        if (kc + S - 1 < nk) {
            if (!AF32) issueA_cp(kc + S - 1);
            issueB(kc + S - 1);
        }
        asm volatile("cp.async.commit_group;" ::: "memory");

        const uint32_t stA = sb + (uint32_t)((AF32 ? (kc & 1) : (kc % S)) * TA_B);
        const uint32_t stB = sb + offB0 + (uint32_t)(kc % S) * TB_B;
#pragma unroll
        for (int ks = 0; ks < 2; ks++) {
            uint32_t ah[MI][4], bb[NI / 2][4];
            const uint32_t aoff = (uint32_t)((wm * MI * 16 + (lane & 15)) * ROWB +
                                             ks * 32 + ((lane >> 4) & 1) * 16);
            const uint32_t boff = (uint32_t)((wn * NI * 8 + ((lane >> 4) & 1) * 8 +
                                              (lane & 7)) * ROWB +
                                             ks * 32 + ((lane >> 3) & 1) * 16);
#pragma unroll
            for (int mi = 0; mi < MI; mi++)
                ldm_x4(ah[mi], stA + aoff + mi * 16 * ROWB);
#pragma unroll
            for (int nj = 0; nj < NI / 2; nj++)
                ldm_x4(bb[nj], stB + boff + nj * 16 * ROWB);
#pragma unroll
            for (int ni = 0; ni < NI; ni++)
#pragma unroll
                for (int mi = 0; mi < MI; mi++)
                    mma_f16(acc[mi][ni], ah[mi], &bb[ni >> 1][2 * (ni & 1)]);
        }
    }

    // ---- epilogue ----
    const float sc = (MODE == 1) ? *scale_p : 0.0f;
    const int er = lane >> 2, ec = 2 * (lane & 3);
#pragma unroll
    for (int mi = 0; mi < MI; mi++)
#pragma unroll
        for (int ni = 0; ni < NI; ni++) {
            const float* a4 = acc[mi][ni];
            const int m0 = bm + wm * MI * 16 + mi * 16 + er;
            const int n0 = bn + wn * NI * 8 + ni * 8 + ec;
#pragma unroll
            for (int h = 0; h < 2; h++) {
                const size_t off = (size_t)(m0 + 8 * h) * N + n0;
                if (MODE == 2) {
                    *reinterpret_cast<__half2*>(Ch + off) =
                        __floats2half2_rn(a4[2 * h + 0], a4[2 * h + 1]);
                } else {
                    float2 r = *reinterpret_cast<const float2*>(residual + off);
                    float2 o;
                    o.x = r.x + sc * a4[2 * h + 0];
                    o.y = r.y + sc * a4[2 * h + 1];
                    *reinterpret_cast<float2*>(Cf + off) = o;
                }
            }
        }
}

// smem sizes
#define TA128  (128 * ROWB)
#define TB256  (256 * ROWB)
#define TB128  (128 * ROWB)
#define TILE64 (64 * ROWB)
#define SMEM_G4 (2 * TA128 + 4 * TB256)     // GEMM4: A 2 stg + B 4 -> 102400
#define SMEM_G5 (4 * TA128 + 4 * TB128)     // GEMM5: 81920 (2 CTA/SM)
#define SMEM_SM (6 * TILE64 + 6 * TILE64)   // small S=6: 61440

// ---------------- host ----------------
extern "C" void kernel_launch(void* const* d_in, const int* in_sizes, int n_in,
                              void* d_out, int out_size) {
    const float* hs     = (const float*)d_in[0];
    const float* w_down = (const float*)d_in[1];
    const float* w_up   = (const float*)d_in[2];
    const float* w1     = (const float*)d_in[3];
    const float* w2     = (const float*)d_in[4];
    const float* scale  = (const float*)d_in[5];
    float* out          = (float*)d_out;

#define SYM(p, s) cudaGetSymbolAddress((void**)&p, s)
    hf *wu_h, *w2_h, *w1T_h, *wdT_h, *tmp_h, *wA_h, *o_h;
    SYM(wu_h, g_wup_h); SYM(w2_h, g_w2_h);
    SYM(w1T_h, g_w1T_h); SYM(wdT_h, g_wdT_h);
    SYM(tmp_h, g_tmp_h); SYM(wA_h, g_wA_h);
    SYM(o_h, g_o_h);
#undef SYM

    // GEMM4: CTA 128x256, 8 warps (2x4), warp 64x64, AF32 loader, OCC1
    cudaFuncSetAttribute((const void*)gemm_mma<4, 8, 2, 4, 4, 2, 1, 1>,
                         cudaFuncAttributeMaxDynamicSharedMemorySize, SMEM_G4);
    // GEMM5: CTA 128x128, 8 warps (2x4), warp 64x32, OCC2
    cudaFuncSetAttribute((const void*)gemm_mma<4, 4, 2, 4, 4, 1, 2, 0>,
                         cudaFuncAttributeMaxDynamicSharedMemorySize, SMEM_G5);
    // small: CTA 64x64, 4 warps, S=6, OCC4
    cudaFuncSetAttribute((const void*)gemm_mma<2, 4, 2, 2, 6, 2, 4, 0>,
                         cudaFuncAttributeMaxDynamicSharedMemorySize, SMEM_SM);

    // 0: all prep (transposes + converts)
    prep_all<<<2560, 256>>>(w1, w1T_h, w_down, wdT_h,
                            (const float4*)w_up, (__half2*)wu_h,
                            (const float4*)w2, (__half2*)w2_h);

    // 1: tmp = w2 @ w1  (M=512, N=512, K=512)
    gemm_mma<2, 4, 2, 2, 6, 2, 4, 0><<<dim3(8, 8), 128, SMEM_SM>>>(
        w2_h, nullptr, w1T_h, 512, 512, tmp_h, nullptr, nullptr, nullptr);

    // 2: wA = tmp @ w_down  (M=512, N=2048, K=512)
    gemm_mma<2, 4, 2, 2, 6, 2, 4, 0><<<dim3(32, 8), 128, SMEM_SM>>>(
        tmp_h, nullptr, wdT_h, 2048, 512, wA_h, nullptr, nullptr, nullptr);

    // 3: o = hs @ wA^T  (M=8192, N=512, K=2048; A converted in-loader)
    gemm_mma<4, 8, 2, 4, 4, 2, 1, 1><<<dim3(2, 64), 256, SMEM_G4>>>(
        nullptr, hs, wA_h, 512, 2048, o_h, nullptr, nullptr, nullptr);

    // 4: out = res + s * (o @ w_up^T)  (M=8192, N=2048, K=512)
    gemm_mma<4, 4, 2, 4, 4, 1, 2, 0><<<dim3(16, 64), 256, SMEM_G5>>>(
        o_h, nullptr, wu_h, 2048, 512, nullptr, out, hs, scale);
}